// round 15
// baseline (speedup 1.0000x reference)
#include <cuda_runtime.h>
#include <cuda_fp16.h>
#include <cstdint>
#include <math.h>

#define DIMC 768
#define HEADS 12
#define NB 8
#define NTOK 1024
#define DH 64
#define NBH (NB * HEADS)

// ---------------------------------------------------------------------------
// Global scratch (fp16 hi/lo splits; lo only where precision requires)
// ---------------------------------------------------------------------------
__device__ __half g_Xh[(size_t)NB * NTOK * DIMC];          // tokens [m][k]
__device__ __half g_Xl[(size_t)NB * NTOK * DIMC];
__device__ __half g_Wqh[(size_t)3 * DIMC * DIMC];          // w_qkv^T permuted [j'][k]
__device__ __half g_Wql[(size_t)3 * DIMC * DIMC];
__device__ __half g_Wph[(size_t)DIMC * DIMC];              // w_proj^T [j][k] (hi only)
__device__ __half g_Ch[(size_t)NB * NTOK * DIMC];          // ctx [m][k] (hi only)
// Attention operands
__device__ __half g_Qh[(size_t)NBH * NTOK * DH];           // [bh][n][d] (x8 via W)
__device__ __half g_Ql[(size_t)NBH * NTOK * DH];
__device__ __half g_Kh[(size_t)NBH * NTOK * DH];           // [bh][n][d]
__device__ __half g_Kl[(size_t)NBH * NTOK * DH];
__device__ __half g_Vh[(size_t)NBH * DH * NTOK];           // [bh][d][n] (hi only)

// ---------------------------------------------------------------------------
// Helpers
// ---------------------------------------------------------------------------
__device__ __forceinline__ uint32_t smem_to_u32(const void* p) {
    uint32_t a;
    asm("{ .reg .u64 t; cvta.to.shared.u64 t, %1; cvt.u32.u64 %0, t; }" : "=r"(a) : "l"(p));
    return a;
}
__device__ __forceinline__ void ldsm_x4(uint32_t* r, uint32_t a) {
    asm volatile("ldmatrix.sync.aligned.m8n8.x4.shared.b16 {%0,%1,%2,%3}, [%4];"
        : "=r"(r[0]), "=r"(r[1]), "=r"(r[2]), "=r"(r[3]) : "r"(a));
}
__device__ __forceinline__ void mma_f16(float* d, const uint32_t* a, const uint32_t* b) {
    asm("mma.sync.aligned.m16n8k16.row.col.f32.f16.f16.f32 "
        "{%0,%1,%2,%3}, {%4,%5,%6,%7}, {%8,%9}, {%0,%1,%2,%3};"
        : "+f"(d[0]), "+f"(d[1]), "+f"(d[2]), "+f"(d[3])
        : "r"(a[0]), "r"(a[1]), "r"(a[2]), "r"(a[3]), "r"(b[0]), "r"(b[1]));
}
__device__ __forceinline__ void mma_f16acc(uint32_t* d, const uint32_t* a, const uint32_t* b) {
    asm("mma.sync.aligned.m16n8k16.row.col.f16.f16.f16.f16 "
        "{%0,%1}, {%2,%3,%4,%5}, {%6,%7}, {%0,%1};"
        : "+r"(d[0]), "+r"(d[1])
        : "r"(a[0]), "r"(a[1]), "r"(a[2]), "r"(a[3]), "r"(b[0]), "r"(b[1]));
}
__device__ __forceinline__ float2 h2f2(uint32_t p) {
    return __half22float2(*(__half2*)&p);
}
__device__ __forceinline__ uint32_t pack_f16(float lo, float hi) {
    uint32_t r;
    asm("cvt.rn.f16x2.f32 %0, %1, %2;" : "=r"(r) : "f"(hi), "f"(lo));
    return r;
}
__device__ __forceinline__ uint32_t pack2h(__half a, __half b) {
    return ((uint32_t)*(uint16_t*)&b << 16) | *(uint16_t*)&a;
}
__device__ __forceinline__ void cp_async16(uint32_t sa, const void* g) {
    asm volatile("cp.async.cg.shared.global [%0], [%1], 16;" :: "r"(sa), "l"(g));
}
#define CP_COMMIT() asm volatile("cp.async.commit_group;" ::: "memory")
#define CP_WAIT(N)  asm volatile("cp.async.wait_group %0;" :: "n"(N) : "memory")

// ---------------------------------------------------------------------------
// Fused split kernel (unchanged from R14)
// ---------------------------------------------------------------------------
__global__ void split_all_kernel(const float* __restrict__ x,
                                 const float* __restrict__ wq,
                                 const float* __restrict__ wp)
{
    __shared__ float tile[32][33];
    int z = blockIdx.z;
    int tx = threadIdx.x & 31, ty = threadIdx.x >> 5;
    int c0 = blockIdx.x << 5, r0 = blockIdx.y << 5;

    if (z < NB) {
        if (c0 >= NTOK) return;
        const float* src = x + (size_t)z * DIMC * NTOK;
#pragma unroll
        for (int i = 0; i < 32; i += 8)
            tile[ty + i][tx] = src[(size_t)(r0 + ty + i) * NTOK + c0 + tx];
        __syncthreads();
        size_t bo = (size_t)z * NTOK * DIMC;
#pragma unroll
        for (int i = 0; i < 32; i += 8) {
            float v = tile[tx][ty + i];
            __half hv = __float2half(v);
            size_t o = bo + (size_t)(c0 + ty + i) * DIMC + (r0 + tx);
            g_Xh[o] = hv;
            g_Xl[o] = __float2half(v - __half2float(hv));
        }
    } else if (z == NB) {
#pragma unroll
        for (int i = 0; i < 32; i += 8)
            tile[ty + i][tx] = wq[(size_t)(r0 + ty + i) * (3 * DIMC) + c0 + tx];
        __syncthreads();
#pragma unroll
        for (int i = 0; i < 32; i += 8) {
            int j = c0 + ty + i;
            float v = tile[tx][ty + i];
            int rem = j % 36, d = j / 36;
            if (rem < 12) v *= 8.f;
            int jp = rem * 64 + d;
            __half hv = __float2half(v);
            float lo = v - __half2float(hv);
            size_t o = (size_t)jp * DIMC + r0 + tx;
            g_Wqh[o] = hv;
            g_Wql[o] = __float2half(lo);
        }
    } else {
        if (c0 >= DIMC) return;
#pragma unroll
        for (int i = 0; i < 32; i += 8)
            tile[ty + i][tx] = wp[(size_t)(r0 + ty + i) * DIMC + c0 + tx];
        __syncthreads();
#pragma unroll
        for (int i = 0; i < 32; i += 8) {
            float v = tile[tx][ty + i];
            size_t o = (size_t)(c0 + ty + i) * DIMC + (r0 + tx);
            g_Wph[o] = __float2half(v);
        }
    }
}

// ---------------------------------------------------------------------------
// qkv GEMM: 128m x 256n block tile, 16 warps of 32x64 (R12 config)
// ---------------------------------------------------------------------------
#define SA_STRIDE 72
#define A_TILE_B (128 * SA_STRIDE * 2)           // 18432
#define B_TILE_B (256 * SA_STRIDE * 2)           // 36864
#define STAGE_BYTES (2 * A_TILE_B + 2 * B_TILE_B) // 110592
#define GEMM_SMEM (2 * STAGE_BYTES)              // 221184
#define GTHREADS 512

#define OFF_AH 0
#define OFF_AL A_TILE_B
#define OFF_BH (2 * A_TILE_B)
#define OFF_BL (2 * A_TILE_B + B_TILE_B)

__device__ __forceinline__ void load_tileA_async(const __half* __restrict__ g,
    size_t row0, uint32_t sdst, int kc, int t)
{
#pragma unroll
    for (int p = 0; p < 2; p++) {
        int lin = p * GTHREADS + t;
        int row = lin >> 3, seg = lin & 7;
        cp_async16(sdst + (uint32_t)(row * SA_STRIDE + seg * 8) * 2,
                   g + (row0 + row) * (size_t)DIMC + kc + seg * 8);
    }
}
__device__ __forceinline__ void load_tileB_async(const __half* __restrict__ g,
    size_t row0, uint32_t sdst, int kc, int t)
{
#pragma unroll
    for (int p = 0; p < 4; p++) {
        int lin = p * GTHREADS + t;
        int row = lin >> 3, seg = lin & 7;
        cp_async16(sdst + (uint32_t)(row * SA_STRIDE + seg * 8) * 2,
                   g + (row0 + row) * (size_t)DIMC + kc + seg * 8);
    }
}

__global__ void __launch_bounds__(GTHREADS, 1) qkv_mma() {
    extern __shared__ char smem[];
    const uint32_t sb = smem_to_u32(smem);
    const __half* Ah = g_Xh;
    const __half* Al = g_Xl;
    const __half* Bh = g_Wqh;
    const __half* Bl = g_Wql;

    int t = threadIdx.x, lane = t & 31, wid = t >> 5;
    int wm = (wid & 3) * 32;
    int wn = (wid >> 2) * 64;

    size_t m0 = (size_t)blockIdx.x * 128;
    int by = blockIdx.y;
    int j0 = by * 256;
    const int nterms = (by < 6) ? 3 : 1;

    float acc[2][8][4] = {};
    int arow = lane & 15;
    int acolp = (lane >> 4) << 3;
    int brow = (lane & 7) + ((lane >> 4) & 1) * 8;
    int bcolp = ((lane >> 3) & 1) * 8;

    {
        uint32_t st = sb;
        load_tileA_async(Ah, m0, st + OFF_AH, 0, t);
        if (nterms >= 2) load_tileA_async(Al, m0, st + OFF_AL, 0, t);
        load_tileB_async(Bh, (size_t)j0, st + OFF_BH, 0, t);
        if (nterms >= 3) load_tileB_async(Bl, (size_t)j0, st + OFF_BL, 0, t);
        CP_COMMIT();
    }

    for (int c = 0; c < 12; c++) {
        CP_WAIT(0);
        __syncthreads();
        if (c + 1 < 12) {
            uint32_t st = sb + ((c + 1) & 1) * STAGE_BYTES;
            int kc = (c + 1) * 64;
            load_tileA_async(Ah, m0, st + OFF_AH, kc, t);
            if (nterms >= 2) load_tileA_async(Al, m0, st + OFF_AL, kc, t);
            load_tileB_async(Bh, (size_t)j0, st + OFF_BH, kc, t);
            if (nterms >= 3) load_tileB_async(Bl, (size_t)j0, st + OFF_BL, kc, t);
            CP_COMMIT();
        }

        uint32_t base = sb + (c & 1) * STAGE_BYTES;
#pragma unroll
        for (int ks = 0; ks < 4; ks++) {
            uint32_t ah[2][4], al[2][4];
            int acol = ks * 16 + acolp;
            int bcol = ks * 16 + bcolp;
#pragma unroll
            for (int mt = 0; mt < 2; mt++) {
                uint32_t ad = base + OFF_AH + ((wm + mt * 16 + arow) * SA_STRIDE + acol) * 2;
                ldsm_x4(ah[mt], ad);
                if (nterms >= 2) ldsm_x4(al[mt], ad + (OFF_AL - OFF_AH));
            }
#pragma unroll
            for (int ntp = 0; ntp < 4; ntp++) {
                uint32_t bh[4], bl[4];
                uint32_t bd = base + OFF_BH + ((wn + ntp * 16 + brow) * SA_STRIDE + bcol) * 2;
                ldsm_x4(bh, bd);
                if (nterms >= 3) ldsm_x4(bl, bd + (OFF_BL - OFF_BH));
#pragma unroll
                for (int mt = 0; mt < 2; mt++) {
                    mma_f16(acc[mt][ntp * 2],     ah[mt], &bh[0]);
                    mma_f16(acc[mt][ntp * 2 + 1], ah[mt], &bh[2]);
                }
                if (nterms >= 2) {
#pragma unroll
                    for (int mt = 0; mt < 2; mt++) {
                        mma_f16(acc[mt][ntp * 2],     al[mt], &bh[0]);
                        mma_f16(acc[mt][ntp * 2 + 1], al[mt], &bh[2]);
                    }
                }
                if (nterms >= 3) {
#pragma unroll
                    for (int mt = 0; mt < 2; mt++) {
                        mma_f16(acc[mt][ntp * 2],     ah[mt], &bl[0]);
                        mma_f16(acc[mt][ntp * 2 + 1], ah[mt], &bl[2]);
                    }
                }
            }
        }
    }
    __syncthreads();

    float* Cs = (float*)smem;
    int g = lane >> 2, tq = lane & 3;
    int bq = (int)(m0 >> 10);
    int n0 = (int)(m0 & 1023);

    int kq = by / 3;
    if (kq < 2) {
#pragma unroll
        for (int mt = 0; mt < 2; mt++)
#pragma unroll
            for (int nt = 0; nt < 8; nt++) {
                int r = wm + mt * 16 + g;
                int cc = wn + nt * 8 + tq * 2;
                *(float2*)&Cs[r * 260 + cc]       = make_float2(acc[mt][nt][0], acc[mt][nt][1]);
                *(float2*)&Cs[(r + 8) * 260 + cc] = make_float2(acc[mt][nt][2], acc[mt][nt][3]);
            }
        __syncthreads();
        __half* Dh = (kq == 0) ? g_Qh : g_Kh;
        __half* Dl = (kq == 0) ? g_Ql : g_Kl;
#pragma unroll
        for (int it = 0; it < 8; it++) {
            int idx = it * GTHREADS + t;
            int kqh_l = idx >> 10;
            int m = (idx >> 3) & 127;
            int dseg = idx & 7;
            int h = (by * 4 + kqh_l) % 12;
            int bh_i = bq * 12 + h;
            float f[8];
            *(float4*)&f[0] = *(float4*)&Cs[m * 260 + kqh_l * 64 + dseg * 8];
            *(float4*)&f[4] = *(float4*)&Cs[m * 260 + kqh_l * 64 + dseg * 8 + 4];
            uint32_t hp[4], lp[4];
#pragma unroll
            for (int q = 0; q < 4; q++) {
                __half h0 = __float2half(f[2 * q]);
                __half h1 = __float2half(f[2 * q + 1]);
                hp[q] = pack2h(h0, h1);
                lp[q] = pack_f16(f[2 * q] - __half2float(h0),
                                 f[2 * q + 1] - __half2float(h1));
            }
            size_t o = ((size_t)bh_i * NTOK + n0 + m) * DH + dseg * 8;
            *(uint4*)(Dh + o) = *(uint4*)hp;
            *(uint4*)(Dl + o) = *(uint4*)lp;
        }
    } else {
#pragma unroll
        for (int mt = 0; mt < 2; mt++)
#pragma unroll
            for (int nt = 0; nt < 8; nt++) {
                int ml = wm + mt * 16 + g;
                int jl = wn + nt * 8 + tq * 2;
                Cs[jl * 132 + ml]           = acc[mt][nt][0];
                Cs[(jl + 1) * 132 + ml]     = acc[mt][nt][1];
                Cs[jl * 132 + ml + 8]       = acc[mt][nt][2];
                Cs[(jl + 1) * 132 + ml + 8] = acc[mt][nt][3];
            }
        __syncthreads();
#pragma unroll
        for (int it = 0; it < 8; it++) {
            int idx = it * GTHREADS + t;
            int jl = idx >> 4;
            int seg = idx & 15;
            int kqh_l = jl >> 6, d = jl & 63;
            int h = (by * 4 + kqh_l) % 12;
            int bh_i = bq * 12 + h;
            float f[8];
            *(float4*)&f[0] = *(float4*)&Cs[jl * 132 + seg * 8];
            *(float4*)&f[4] = *(float4*)&Cs[jl * 132 + seg * 8 + 4];
            uint32_t hp[4];
#pragma unroll
            for (int q = 0; q < 4; q++)
                hp[q] = pack_f16(f[2 * q], f[2 * q + 1]);
            size_t o = ((size_t)bh_i * DH + d) * NTOK + n0 + seg * 8;
            *(uint4*)(g_Vh + o) = *(uint4*)hp;
        }
    }
}

// ---------------------------------------------------------------------------
// proj GEMM: 128m x 128n tile (better wave quantization at grid 384),
// 512 threads = 16 warps (4m x 4n, 32x32), 1-term, double-buffered.
// ---------------------------------------------------------------------------
#define PSTAGE (2 * A_TILE_B)                    // 36864 (Ah + Bh)
#define PROJ_SMEM (2 * PSTAGE)                   // 73728

__global__ void __launch_bounds__(GTHREADS, 1) proj_mma(float* __restrict__ out) {
    extern __shared__ char smem[];
    const uint32_t sb = smem_to_u32(smem);

    int t = threadIdx.x, lane = t & 31, wid = t >> 5;
    int wm = (wid & 3) * 32, wn = (wid >> 2) * 32;

    size_t m0 = (size_t)blockIdx.x * 128;
    int j0 = blockIdx.y * 128;

    float acc[2][4][4] = {};
    int arow = lane & 15;
    int acolp = (lane >> 4) << 3;
    int brow = (lane & 7) + ((lane >> 4) & 1) * 8;
    int bcolp = ((lane >> 3) & 1) * 8;

    {
        load_tileA_async(g_Ch, m0, sb, 0, t);
        load_tileA_async(g_Wph, (size_t)j0, sb + A_TILE_B, 0, t);
        CP_COMMIT();
    }

    for (int c = 0; c < 12; c++) {
        CP_WAIT(0);
        __syncthreads();
        if (c + 1 < 12) {
            uint32_t st = sb + ((c + 1) & 1) * PSTAGE;
            int kc = (c + 1) * 64;
            load_tileA_async(g_Ch, m0, st, kc, t);
            load_tileA_async(g_Wph, (size_t)j0, st + A_TILE_B, kc, t);
            CP_COMMIT();
        }

        uint32_t base = sb + (c & 1) * PSTAGE;
#pragma unroll
        for (int ks = 0; ks < 4; ks++) {
            uint32_t ah[2][4], bh[2][4];
            int acol = ks * 16 + acolp;
            int bcol = ks * 16 + bcolp;
#pragma unroll
            for (int mt = 0; mt < 2; mt++)
                ldsm_x4(ah[mt], base + ((wm + mt * 16 + arow) * SA_STRIDE + acol) * 2);
#pragma unroll
            for (int ntp = 0; ntp < 2; ntp++)
                ldsm_x4(bh[ntp], base + A_TILE_B + ((wn + ntp * 16 + brow) * SA_STRIDE + bcol) * 2);
#pragma unroll
            for (int mt = 0; mt < 2; mt++)
#pragma unroll
                for (int nt = 0; nt < 4; nt++)
                    mma_f16(acc[mt][nt], ah[mt], &bh[nt >> 1][(nt & 1) * 2]);
        }
    }
    __syncthreads();

    float* Cs = (float*)smem;
    int g = lane >> 2, tq = lane & 3;
    int bq = (int)(m0 >> 10);
    int n0 = (int)(m0 & 1023);

#pragma unroll
    for (int mt = 0; mt < 2; mt++)
#pragma unroll
        for (int nt = 0; nt < 4; nt++) {
            int ml = wm + mt * 16 + g;
            int jl = wn + nt * 8 + tq * 2;
            Cs[jl * 132 + ml]           = acc[mt][nt][0];
            Cs[(jl + 1) * 132 + ml]     = acc[mt][nt][1];
            Cs[jl * 132 + ml + 8]       = acc[mt][nt][2];
            Cs[(jl + 1) * 132 + ml + 8] = acc[mt][nt][3];
        }
    __syncthreads();
#pragma unroll
    for (int r = 0; r < 8; r++) {
        int e = r * GTHREADS + t;
        int jl = e >> 5, seg = e & 31;
        float4 v = *(float4*)&Cs[jl * 132 + seg * 4];
        *(float4*)&out[((size_t)bq * DIMC + j0 + jl) * NTOK + n0 + seg * 4] = v;
    }
}

// ---------------------------------------------------------------------------
// Flash attention (R12 config): 128 q rows, 8 warps x 16 rows, 2 blocks/SM.
// ---------------------------------------------------------------------------
#define KV_TILE 9216
#define KV_STAGE (3 * KV_TILE)                    // 27648
#define ATT_Q (2 * 18432)                         // 36864
#define ATT_SMEM (ATT_Q + 2 * KV_STAGE)           // 92160

__global__ void __launch_bounds__(256, 2) attn_mma() {
    extern __shared__ char sm[];
    const uint32_t sb = smem_to_u32(sm);
    const uint32_t oQh = 0, oQl = 18432;
    __half* sQh = (__half*)(sm + oQh);
    __half* sQl = (__half*)(sm + oQl);

    int t = threadIdx.x, lane = t & 31, wid = t >> 5;
    int bh = blockIdx.y, qn0 = blockIdx.x << 7;

    const __half* Qhg = g_Qh + ((size_t)bh * NTOK + qn0) * DH;
    const __half* Qlg = g_Ql + ((size_t)bh * NTOK + qn0) * DH;
    const __half* Khg = g_Kh + (size_t)bh * NTOK * DH;
    const __half* Klg = g_Kl + (size_t)bh * NTOK * DH;
    const __half* Vhg = g_Vh + (size_t)bh * DH * NTOK;

    {
        uint32_t st = sb + ATT_Q;
#pragma unroll
        for (int p = 0; p < 2; p++) {
            int idx = p * 256 + t;
            int row = idx >> 3, seg = idx & 7;
            uint32_t so = (uint32_t)(row * 72 + seg * 8) * 2;
            cp_async16(st + so,               Khg + (size_t)row * DH + seg * 8);
            cp_async16(st + KV_TILE + so,     Klg + (size_t)row * DH + seg * 8);
            cp_async16(st + 2 * KV_TILE + so, Vhg + (size_t)row * NTOK + seg * 8);
        }
        CP_COMMIT();
    }

#pragma unroll
    for (int p = 0; p < 4; p++) {
        int idx = p * 256 + t;
        int row = idx >> 3, seg = idx & 7;
        *(uint4*)(sQh + row * 72 + seg * 8) = *(const uint4*)(Qhg + row * DH + seg * 8);
        *(uint4*)(sQl + row * 72 + seg * 8) = *(const uint4*)(Qlg + row * DH + seg * 8);
    }

    float o[8][4] = {};
    float m0 = -1e30f, m1 = -1e30f, l0 = 0.f, l1 = 0.f;

    int arow = lane & 15, acolp = (lane >> 4) << 3;
    int brow = (lane & 7) + ((lane >> 4) & 1) * 8;
    int bcolp = ((lane >> 3) & 1) * 8;

    for (int kt = 0; kt < 16; kt++) {
        CP_WAIT(0);
        __syncthreads();
        if (kt + 1 < 16) {
            uint32_t st = sb + ATT_Q + ((kt + 1) & 1) * KV_STAGE;
            int jb = (kt + 1) * 64;
#pragma unroll
            for (int p = 0; p < 2; p++) {
                int idx = p * 256 + t;
                int row = idx >> 3, seg = idx & 7;
                uint32_t so = (uint32_t)(row * 72 + seg * 8) * 2;
                cp_async16(st + so,               Khg + (size_t)(jb + row) * DH + seg * 8);
                cp_async16(st + KV_TILE + so,     Klg + (size_t)(jb + row) * DH + seg * 8);
                cp_async16(st + 2 * KV_TILE + so, Vhg + (size_t)row * NTOK + jb + seg * 8);
            }
            CP_COMMIT();
        }

        uint32_t kv = sb + ATT_Q + (kt & 1) * KV_STAGE;

        float s[8][4] = {};
        uint32_t sc[8][2] = {};
#pragma unroll
        for (int ks = 0; ks < 4; ks++) {
            uint32_t ah[4], al[4];
            uint32_t aq = sb + oQh + ((wid * 16 + arow) * 72 + ks * 16 + acolp) * 2;
            ldsm_x4(ah, aq);
            ldsm_x4(al, aq + (oQl - oQh));
#pragma unroll
            for (int ntp = 0; ntp < 4; ntp++) {
                uint32_t bhf[4], blf[4];
                uint32_t ba = kv + ((ntp * 16 + brow) * 72 + ks * 16 + bcolp) * 2;
                ldsm_x4(bhf, ba);
                ldsm_x4(blf, ba + KV_TILE);
                int nt = ntp * 2;
                mma_f16(s[nt],     ah, &bhf[0]);
                mma_f16(s[nt + 1], ah, &bhf[2]);
                mma_f16acc(sc[nt],     al, &bhf[0]);
                mma_f16acc(sc[nt + 1], al, &bhf[2]);
                mma_f16acc(sc[nt],     ah, &blf[0]);
                mma_f16acc(sc[nt + 1], ah, &blf[2]);
            }
        }
#pragma unroll
        for (int nt = 0; nt < 8; nt++) {
            float2 c01 = h2f2(sc[nt][0]);
            float2 c23 = h2f2(sc[nt][1]);
            s[nt][0] += c01.x;
            s[nt][1] += c01.y;
            s[nt][2] += c23.x;
            s[nt][3] += c23.y;
        }

        float rm0 = -1e30f, rm1 = -1e30f;
#pragma unroll
        for (int nt = 0; nt < 8; nt++) {
            rm0 = fmaxf(rm0, fmaxf(s[nt][0], s[nt][1]));
            rm1 = fmaxf(rm1, fmaxf(s[nt][2], s[nt][3]));
        }
        rm0 = fmaxf(rm0, __shfl_xor_sync(0xffffffffu, rm0, 1));
        rm0 = fmaxf(rm0, __shfl_xor_sync(0xffffffffu, rm0, 2));
        rm1 = fmaxf(rm1, __shfl_xor_sync(0xffffffffu, rm1, 1));
        rm1 = fmaxf(rm1, __shfl_xor_sync(0xffffffffu, rm1, 2));
        float mn0 = fmaxf(m0, rm0), mn1 = fmaxf(m1, rm1);
        float alpha0 = __expf(m0 - mn0), alpha1 = __expf(m1 - mn1);
        m0 = mn0; m1 = mn1;
        float rs0 = 0.f, rs1 = 0.f;
#pragma unroll
        for (int nt = 0; nt < 8; nt++) {
            s[nt][0] = __expf(s[nt][0] - mn0);
            s[nt][1] = __expf(s[nt][1] - mn0);
            s[nt][2] = __expf(s[nt][2] - mn1);
            s[nt][3] = __expf(s[nt][3] - mn1);
            rs0 += s[nt][0] + s[nt][1];
            rs1 += s[nt][2] + s[nt][3];
        }
        rs0 += __shfl_xor_sync(0xffffffffu, rs0, 1);
        rs0 += __shfl_xor_sync(0xffffffffu, rs0, 2);
        rs1 += __shfl_xor_sync(0xffffffffu, rs1, 1);
        rs1 += __shfl_xor_sync(0xffffffffu, rs1, 2);
        l0 = l0 * alpha0 + rs0;
        l1 = l1 * alpha1 + rs1;
#pragma unroll
        for (int nt = 0; nt < 8; nt++) {
            o[nt][0] *= alpha0; o[nt][1] *= alpha0;
            o[nt][2] *= alpha1; o[nt][3] *= alpha1;
        }

        uint32_t pah[4][4];
#pragma unroll
        for (int ks = 0; ks < 4; ks++) {
#pragma unroll
            for (int q = 0; q < 4; q++) {
                int nt = ks * 2 + (q >> 1);
                pah[ks][q] = pack_f16(s[nt][(q & 1) * 2], s[nt][(q & 1) * 2 + 1]);
            }
        }

#pragma unroll
        for (int ks = 0; ks < 4; ks++) {
#pragma unroll
            for (int ntp = 0; ntp < 4; ntp++) {
                uint32_t vhf[4];
                uint32_t va = kv + 2 * KV_TILE + ((ntp * 16 + brow) * 72 + ks * 16 + bcolp) * 2;
                ldsm_x4(vhf, va);
                mma_f16(o[ntp * 2],     pah[ks], &vhf[0]);
                mma_f16(o[ntp * 2 + 1], pah[ks], &vhf[2]);
            }
        }
    }

    float inv0 = 1.f / l0, inv1 = 1.f / l1;
    int b = bh / HEADS, h = bh % HEADS;
    int r0 = qn0 + wid * 16 + (lane >> 2);
    int cb = h * DH + (lane & 3) * 2;
#pragma unroll
    for (int nt = 0; nt < 8; nt++) {
        uint32_t hp0 = pack_f16(o[nt][0] * inv0, o[nt][1] * inv0);
        uint32_t hp1 = pack_f16(o[nt][2] * inv1, o[nt][3] * inv1);
        size_t o0 = ((size_t)b * NTOK + r0) * DIMC + cb + nt * 8;
        size_t o1 = ((size_t)b * NTOK + r0 + 8) * DIMC + cb + nt * 8;
        *(uint32_t*)(g_Ch + o0) = hp0;
        *(uint32_t*)(g_Ch + o1) = hp1;
    }
}

// ---------------------------------------------------------------------------
extern "C" void kernel_launch(void* const* d_in, const int* in_sizes, int n_in,
                              void* d_out, int out_size) {
    const float* x      = (const float*)d_in[0];
    const float* w_qkv  = (const float*)d_in[1];
    const float* w_proj = (const float*)d_in[2];
    float* out = (float*)d_out;

    cudaFuncSetAttribute(qkv_mma,  cudaFuncAttributeMaxDynamicSharedMemorySize, GEMM_SMEM);
    cudaFuncSetAttribute(proj_mma, cudaFuncAttributeMaxDynamicSharedMemorySize, PROJ_SMEM);
    cudaFuncSetAttribute(attn_mma, cudaFuncAttributeMaxDynamicSharedMemorySize, ATT_SMEM);

    split_all_kernel<<<dim3(72, 24, 10), 256>>>(x, w_qkv, w_proj);
    qkv_mma <<<dim3(64, 9), GTHREADS, GEMM_SMEM>>>();
    attn_mma<<<dim3(NTOK / 128, NBH), 256, ATT_SMEM>>>();
    proj_mma<<<dim3(64, 6), GTHREADS, PROJ_SMEM>>>(out);
}

// round 16
// speedup vs baseline: 1.0198x; 1.0198x over previous
#include <cuda_runtime.h>
#include <cuda_fp16.h>
#include <cstdint>
#include <math.h>

#define DIMC 768
#define HEADS 12
#define NB 8
#define NTOK 1024
#define DH 64
#define NBH (NB * HEADS)

// ---------------------------------------------------------------------------
// Global scratch (fp16 hi/lo splits; lo only where precision requires)
// ---------------------------------------------------------------------------
__device__ __half g_Xh[(size_t)NB * NTOK * DIMC];          // tokens [m][k]
__device__ __half g_Xl[(size_t)NB * NTOK * DIMC];
__device__ __half g_Wqh[(size_t)3 * DIMC * DIMC];          // w_qkv^T permuted [j'][k]
__device__ __half g_Wql[(size_t)3 * DIMC * DIMC];
__device__ __half g_Wph[(size_t)DIMC * DIMC];              // w_proj^T [j][k] (hi only)
__device__ __half g_Ch[(size_t)NB * NTOK * DIMC];          // ctx [m][k] (hi only)
// Attention operands
__device__ __half g_Qh[(size_t)NBH * NTOK * DH];           // [bh][n][d] (x8 via W)
__device__ __half g_Ql[(size_t)NBH * NTOK * DH];
__device__ __half g_Kh[(size_t)NBH * NTOK * DH];           // [bh][n][d]
__device__ __half g_Kl[(size_t)NBH * NTOK * DH];
__device__ __half g_Vh[(size_t)NBH * DH * NTOK];           // [bh][d][n] (hi only)

// ---------------------------------------------------------------------------
// Helpers
// ---------------------------------------------------------------------------
__device__ __forceinline__ uint32_t smem_to_u32(const void* p) {
    uint32_t a;
    asm("{ .reg .u64 t; cvta.to.shared.u64 t, %1; cvt.u32.u64 %0, t; }" : "=r"(a) : "l"(p));
    return a;
}
__device__ __forceinline__ void ldsm_x4(uint32_t* r, uint32_t a) {
    asm volatile("ldmatrix.sync.aligned.m8n8.x4.shared.b16 {%0,%1,%2,%3}, [%4];"
        : "=r"(r[0]), "=r"(r[1]), "=r"(r[2]), "=r"(r[3]) : "r"(a));
}
__device__ __forceinline__ void mma_f16(float* d, const uint32_t* a, const uint32_t* b) {
    asm("mma.sync.aligned.m16n8k16.row.col.f32.f16.f16.f32 "
        "{%0,%1,%2,%3}, {%4,%5,%6,%7}, {%8,%9}, {%0,%1,%2,%3};"
        : "+f"(d[0]), "+f"(d[1]), "+f"(d[2]), "+f"(d[3])
        : "r"(a[0]), "r"(a[1]), "r"(a[2]), "r"(a[3]), "r"(b[0]), "r"(b[1]));
}
__device__ __forceinline__ void mma_f16acc(uint32_t* d, const uint32_t* a, const uint32_t* b) {
    asm("mma.sync.aligned.m16n8k16.row.col.f16.f16.f16.f16 "
        "{%0,%1}, {%2,%3,%4,%5}, {%6,%7}, {%0,%1};"
        : "+r"(d[0]), "+r"(d[1])
        : "r"(a[0]), "r"(a[1]), "r"(a[2]), "r"(a[3]), "r"(b[0]), "r"(b[1]));
}
__device__ __forceinline__ float2 h2f2(uint32_t p) {
    return __half22float2(*(__half2*)&p);
}
__device__ __forceinline__ uint32_t pack_f16(float lo, float hi) {
    uint32_t r;
    asm("cvt.rn.f16x2.f32 %0, %1, %2;" : "=r"(r) : "f"(hi), "f"(lo));
    return r;
}
__device__ __forceinline__ uint32_t pack2h(__half a, __half b) {
    return ((uint32_t)*(uint16_t*)&b << 16) | *(uint16_t*)&a;
}
__device__ __forceinline__ void cp_async16(uint32_t sa, const void* g) {
    asm volatile("cp.async.cg.shared.global [%0], [%1], 16;" :: "r"(sa), "l"(g));
}
#define CP_COMMIT() asm volatile("cp.async.commit_group;" ::: "memory")
#define CP_WAIT(N)  asm volatile("cp.async.wait_group %0;" :: "n"(N) : "memory")

// ---------------------------------------------------------------------------
// Fused split kernel (unchanged from R14)
// ---------------------------------------------------------------------------
__global__ void split_all_kernel(const float* __restrict__ x,
                                 const float* __restrict__ wq,
                                 const float* __restrict__ wp)
{
    __shared__ float tile[32][33];
    int z = blockIdx.z;
    int tx = threadIdx.x & 31, ty = threadIdx.x >> 5;
    int c0 = blockIdx.x << 5, r0 = blockIdx.y << 5;

    if (z < NB) {
        if (c0 >= NTOK) return;
        const float* src = x + (size_t)z * DIMC * NTOK;
#pragma unroll
        for (int i = 0; i < 32; i += 8)
            tile[ty + i][tx] = src[(size_t)(r0 + ty + i) * NTOK + c0 + tx];
        __syncthreads();
        size_t bo = (size_t)z * NTOK * DIMC;
#pragma unroll
        for (int i = 0; i < 32; i += 8) {
            float v = tile[tx][ty + i];
            __half hv = __float2half(v);
            size_t o = bo + (size_t)(c0 + ty + i) * DIMC + (r0 + tx);
            g_Xh[o] = hv;
            g_Xl[o] = __float2half(v - __half2float(hv));
        }
    } else if (z == NB) {
#pragma unroll
        for (int i = 0; i < 32; i += 8)
            tile[ty + i][tx] = wq[(size_t)(r0 + ty + i) * (3 * DIMC) + c0 + tx];
        __syncthreads();
#pragma unroll
        for (int i = 0; i < 32; i += 8) {
            int j = c0 + ty + i;
            float v = tile[tx][ty + i];
            int rem = j % 36, d = j / 36;
            if (rem < 12) v *= 8.f;
            int jp = rem * 64 + d;
            __half hv = __float2half(v);
            float lo = v - __half2float(hv);
            size_t o = (size_t)jp * DIMC + r0 + tx;
            g_Wqh[o] = hv;
            g_Wql[o] = __float2half(lo);
        }
    } else {
        if (c0 >= DIMC) return;
#pragma unroll
        for (int i = 0; i < 32; i += 8)
            tile[ty + i][tx] = wp[(size_t)(r0 + ty + i) * DIMC + c0 + tx];
        __syncthreads();
#pragma unroll
        for (int i = 0; i < 32; i += 8) {
            float v = tile[tx][ty + i];
            size_t o = (size_t)(c0 + ty + i) * DIMC + (r0 + tx);
            g_Wph[o] = __float2half(v);
        }
    }
}

// ---------------------------------------------------------------------------
// qkv GEMM: 128m x 256n block tile, 16 warps of 32x64 (R12/R14 config)
// ---------------------------------------------------------------------------
#define SA_STRIDE 72
#define A_TILE_B (128 * SA_STRIDE * 2)           // 18432
#define B_TILE_B (256 * SA_STRIDE * 2)           // 36864
#define STAGE_BYTES (2 * A_TILE_B + 2 * B_TILE_B) // 110592
#define GEMM_SMEM (2 * STAGE_BYTES)              // 221184
#define GTHREADS 512

#define OFF_AH 0
#define OFF_AL A_TILE_B
#define OFF_BH (2 * A_TILE_B)
#define OFF_BL (2 * A_TILE_B + B_TILE_B)

__device__ __forceinline__ void load_tileA_async(const __half* __restrict__ g,
    size_t row0, uint32_t sdst, int kc, int t)
{
#pragma unroll
    for (int p = 0; p < 2; p++) {
        int lin = p * GTHREADS + t;
        int row = lin >> 3, seg = lin & 7;
        cp_async16(sdst + (uint32_t)(row * SA_STRIDE + seg * 8) * 2,
                   g + (row0 + row) * (size_t)DIMC + kc + seg * 8);
    }
}
__device__ __forceinline__ void load_tileB_async(const __half* __restrict__ g,
    size_t row0, uint32_t sdst, int kc, int t)
{
#pragma unroll
    for (int p = 0; p < 4; p++) {
        int lin = p * GTHREADS + t;
        int row = lin >> 3, seg = lin & 7;
        cp_async16(sdst + (uint32_t)(row * SA_STRIDE + seg * 8) * 2,
                   g + (row0 + row) * (size_t)DIMC + kc + seg * 8);
    }
}

__global__ void __launch_bounds__(GTHREADS, 1) qkv_mma() {
    extern __shared__ char smem[];
    const uint32_t sb = smem_to_u32(smem);
    const __half* Ah = g_Xh;
    const __half* Al = g_Xl;
    const __half* Bh = g_Wqh;
    const __half* Bl = g_Wql;

    int t = threadIdx.x, lane = t & 31, wid = t >> 5;
    int wm = (wid & 3) * 32;
    int wn = (wid >> 2) * 64;

    size_t m0 = (size_t)blockIdx.x * 128;
    int by = blockIdx.y;
    int j0 = by * 256;
    const int nterms = (by < 6) ? 3 : 1;

    float acc[2][8][4] = {};
    int arow = lane & 15;
    int acolp = (lane >> 4) << 3;
    int brow = (lane & 7) + ((lane >> 4) & 1) * 8;
    int bcolp = ((lane >> 3) & 1) * 8;

    {
        uint32_t st = sb;
        load_tileA_async(Ah, m0, st + OFF_AH, 0, t);
        if (nterms >= 2) load_tileA_async(Al, m0, st + OFF_AL, 0, t);
        load_tileB_async(Bh, (size_t)j0, st + OFF_BH, 0, t);
        if (nterms >= 3) load_tileB_async(Bl, (size_t)j0, st + OFF_BL, 0, t);
        CP_COMMIT();
    }

    for (int c = 0; c < 12; c++) {
        CP_WAIT(0);
        __syncthreads();
        if (c + 1 < 12) {
            uint32_t st = sb + ((c + 1) & 1) * STAGE_BYTES;
            int kc = (c + 1) * 64;
            load_tileA_async(Ah, m0, st + OFF_AH, kc, t);
            if (nterms >= 2) load_tileA_async(Al, m0, st + OFF_AL, kc, t);
            load_tileB_async(Bh, (size_t)j0, st + OFF_BH, kc, t);
            if (nterms >= 3) load_tileB_async(Bl, (size_t)j0, st + OFF_BL, kc, t);
            CP_COMMIT();
        }

        uint32_t base = sb + (c & 1) * STAGE_BYTES;
#pragma unroll
        for (int ks = 0; ks < 4; ks++) {
            uint32_t ah[2][4], al[2][4];
            int acol = ks * 16 + acolp;
            int bcol = ks * 16 + bcolp;
#pragma unroll
            for (int mt = 0; mt < 2; mt++) {
                uint32_t ad = base + OFF_AH + ((wm + mt * 16 + arow) * SA_STRIDE + acol) * 2;
                ldsm_x4(ah[mt], ad);
                if (nterms >= 2) ldsm_x4(al[mt], ad + (OFF_AL - OFF_AH));
            }
#pragma unroll
            for (int ntp = 0; ntp < 4; ntp++) {
                uint32_t bh[4], bl[4];
                uint32_t bd = base + OFF_BH + ((wn + ntp * 16 + brow) * SA_STRIDE + bcol) * 2;
                ldsm_x4(bh, bd);
                if (nterms >= 3) ldsm_x4(bl, bd + (OFF_BL - OFF_BH));
#pragma unroll
                for (int mt = 0; mt < 2; mt++) {
                    mma_f16(acc[mt][ntp * 2],     ah[mt], &bh[0]);
                    mma_f16(acc[mt][ntp * 2 + 1], ah[mt], &bh[2]);
                }
                if (nterms >= 2) {
#pragma unroll
                    for (int mt = 0; mt < 2; mt++) {
                        mma_f16(acc[mt][ntp * 2],     al[mt], &bh[0]);
                        mma_f16(acc[mt][ntp * 2 + 1], al[mt], &bh[2]);
                    }
                }
                if (nterms >= 3) {
#pragma unroll
                    for (int mt = 0; mt < 2; mt++) {
                        mma_f16(acc[mt][ntp * 2],     ah[mt], &bl[0]);
                        mma_f16(acc[mt][ntp * 2 + 1], ah[mt], &bl[2]);
                    }
                }
            }
        }
    }
    __syncthreads();

    float* Cs = (float*)smem;
    int g = lane >> 2, tq = lane & 3;
    int bq = (int)(m0 >> 10);
    int n0 = (int)(m0 & 1023);

    int kq = by / 3;
    if (kq < 2) {
#pragma unroll
        for (int mt = 0; mt < 2; mt++)
#pragma unroll
            for (int nt = 0; nt < 8; nt++) {
                int r = wm + mt * 16 + g;
                int cc = wn + nt * 8 + tq * 2;
                *(float2*)&Cs[r * 260 + cc]       = make_float2(acc[mt][nt][0], acc[mt][nt][1]);
                *(float2*)&Cs[(r + 8) * 260 + cc] = make_float2(acc[mt][nt][2], acc[mt][nt][3]);
            }
        __syncthreads();
        __half* Dh = (kq == 0) ? g_Qh : g_Kh;
        __half* Dl = (kq == 0) ? g_Ql : g_Kl;
#pragma unroll
        for (int it = 0; it < 8; it++) {
            int idx = it * GTHREADS + t;
            int kqh_l = idx >> 10;
            int m = (idx >> 3) & 127;
            int dseg = idx & 7;
            int h = (by * 4 + kqh_l) % 12;
            int bh_i = bq * 12 + h;
            float f[8];
            *(float4*)&f[0] = *(float4*)&Cs[m * 260 + kqh_l * 64 + dseg * 8];
            *(float4*)&f[4] = *(float4*)&Cs[m * 260 + kqh_l * 64 + dseg * 8 + 4];
            uint32_t hp[4], lp[4];
#pragma unroll
            for (int q = 0; q < 4; q++) {
                __half h0 = __float2half(f[2 * q]);
                __half h1 = __float2half(f[2 * q + 1]);
                hp[q] = pack2h(h0, h1);
                lp[q] = pack_f16(f[2 * q] - __half2float(h0),
                                 f[2 * q + 1] - __half2float(h1));
            }
            size_t o = ((size_t)bh_i * NTOK + n0 + m) * DH + dseg * 8;
            *(uint4*)(Dh + o) = *(uint4*)hp;
            *(uint4*)(Dl + o) = *(uint4*)lp;
        }
    } else {
#pragma unroll
        for (int mt = 0; mt < 2; mt++)
#pragma unroll
            for (int nt = 0; nt < 8; nt++) {
                int ml = wm + mt * 16 + g;
                int jl = wn + nt * 8 + tq * 2;
                Cs[jl * 132 + ml]           = acc[mt][nt][0];
                Cs[(jl + 1) * 132 + ml]     = acc[mt][nt][1];
                Cs[jl * 132 + ml + 8]       = acc[mt][nt][2];
                Cs[(jl + 1) * 132 + ml + 8] = acc[mt][nt][3];
            }
        __syncthreads();
#pragma unroll
        for (int it = 0; it < 8; it++) {
            int idx = it * GTHREADS + t;
            int jl = idx >> 4;
            int seg = idx & 15;
            int kqh_l = jl >> 6, d = jl & 63;
            int h = (by * 4 + kqh_l) % 12;
            int bh_i = bq * 12 + h;
            float f[8];
            *(float4*)&f[0] = *(float4*)&Cs[jl * 132 + seg * 8];
            *(float4*)&f[4] = *(float4*)&Cs[jl * 132 + seg * 8 + 4];
            uint32_t hp[4];
#pragma unroll
            for (int q = 0; q < 4; q++)
                hp[q] = pack_f16(f[2 * q], f[2 * q + 1]);
            size_t o = ((size_t)bh_i * DH + d) * NTOK + n0 + seg * 8;
            *(uint4*)(g_Vh + o) = *(uint4*)hp;
        }
    }
}

// ---------------------------------------------------------------------------
// proj GEMM: 128m x 128n tile, 3-stage cp.async pipeline (CP_WAIT(1) keeps
// one load group in flight under compute), 16 warps (4m x 4n of 32x32).
// ---------------------------------------------------------------------------
#define PSTAGE (2 * A_TILE_B)                    // 36864 (Ah + Bh)
#define PROJ_SMEM (3 * PSTAGE)                   // 110592

__global__ void __launch_bounds__(GTHREADS, 1) proj_mma(float* __restrict__ out) {
    extern __shared__ char smem[];
    const uint32_t sb = smem_to_u32(smem);

    int t = threadIdx.x, lane = t & 31, wid = t >> 5;
    int wm = (wid & 3) * 32, wn = (wid >> 2) * 32;

    size_t m0 = (size_t)blockIdx.x * 128;
    int j0 = blockIdx.y * 128;

    float acc[2][4][4] = {};
    int arow = lane & 15;
    int acolp = (lane >> 4) << 3;
    int brow = (lane & 7) + ((lane >> 4) & 1) * 8;
    int bcolp = ((lane >> 3) & 1) * 8;

    // prefetch chunks 0 and 1 (separate groups)
#pragma unroll
    for (int pc = 0; pc < 2; pc++) {
        uint32_t st = sb + pc * PSTAGE;
        load_tileA_async(g_Ch, m0, st, pc * 64, t);
        load_tileA_async(g_Wph, (size_t)j0, st + A_TILE_B, pc * 64, t);
        CP_COMMIT();
    }

    for (int c = 0; c < 12; c++) {
        CP_WAIT(1);                  // chunk c ready; chunk c+1 may be in flight
        __syncthreads();
        if (c + 2 < 12) {            // prefetch chunk c+2 into freed stage
            uint32_t st = sb + ((c + 2) % 3) * PSTAGE;
            int kc = (c + 2) * 64;
            load_tileA_async(g_Ch, m0, st, kc, t);
            load_tileA_async(g_Wph, (size_t)j0, st + A_TILE_B, kc, t);
            CP_COMMIT();
        }

        uint32_t base = sb + (c % 3) * PSTAGE;
#pragma unroll
        for (int ks = 0; ks < 4; ks++) {
            uint32_t ah[2][4], bh[2][4];
            int acol = ks * 16 + acolp;
            int bcol = ks * 16 + bcolp;
#pragma unroll
            for (int mt = 0; mt < 2; mt++)
                ldsm_x4(ah[mt], base + ((wm + mt * 16 + arow) * SA_STRIDE + acol) * 2);
#pragma unroll
            for (int ntp = 0; ntp < 2; ntp++)
                ldsm_x4(bh[ntp], base + A_TILE_B + ((wn + ntp * 16 + brow) * SA_STRIDE + bcol) * 2);
#pragma unroll
            for (int mt = 0; mt < 2; mt++)
#pragma unroll
                for (int nt = 0; nt < 4; nt++)
                    mma_f16(acc[mt][nt], ah[mt], &bh[nt >> 1][(nt & 1) * 2]);
        }
    }
    CP_WAIT(0);
    __syncthreads();

    float* Cs = (float*)smem;
    int g = lane >> 2, tq = lane & 3;
    int bq = (int)(m0 >> 10);
    int n0 = (int)(m0 & 1023);

#pragma unroll
    for (int mt = 0; mt < 2; mt++)
#pragma unroll
        for (int nt = 0; nt < 4; nt++) {
            int ml = wm + mt * 16 + g;
            int jl = wn + nt * 8 + tq * 2;
            Cs[jl * 132 + ml]           = acc[mt][nt][0];
            Cs[(jl + 1) * 132 + ml]     = acc[mt][nt][1];
            Cs[jl * 132 + ml + 8]       = acc[mt][nt][2];
            Cs[(jl + 1) * 132 + ml + 8] = acc[mt][nt][3];
        }
    __syncthreads();
#pragma unroll
    for (int r = 0; r < 8; r++) {
        int e = r * GTHREADS + t;
        int jl = e >> 5, seg = e & 31;
        float4 v = *(float4*)&Cs[jl * 132 + seg * 4];
        *(float4*)&out[((size_t)bq * DIMC + j0 + jl) * NTOK + n0 + seg * 4] = v;
    }
}

// ---------------------------------------------------------------------------
// Flash attention (R12/R14 config): 128 q rows, 8 warps x 16 rows, 2 blocks/SM.
// ---------------------------------------------------------------------------
#define KV_TILE 9216
#define KV_STAGE (3 * KV_TILE)                    // 27648
#define ATT_Q (2 * 18432)                         // 36864
#define ATT_SMEM (ATT_Q + 2 * KV_STAGE)           // 92160

__global__ void __launch_bounds__(256, 2) attn_mma() {
    extern __shared__ char sm[];
    const uint32_t sb = smem_to_u32(sm);
    const uint32_t oQh = 0, oQl = 18432;
    __half* sQh = (__half*)(sm + oQh);
    __half* sQl = (__half*)(sm + oQl);

    int t = threadIdx.x, lane = t & 31, wid = t >> 5;
    int bh = blockIdx.y, qn0 = blockIdx.x << 7;

    const __half* Qhg = g_Qh + ((size_t)bh * NTOK + qn0) * DH;
    const __half* Qlg = g_Ql + ((size_t)bh * NTOK + qn0) * DH;
    const __half* Khg = g_Kh + (size_t)bh * NTOK * DH;
    const __half* Klg = g_Kl + (size_t)bh * NTOK * DH;
    const __half* Vhg = g_Vh + (size_t)bh * DH * NTOK;

    {
        uint32_t st = sb + ATT_Q;
#pragma unroll
        for (int p = 0; p < 2; p++) {
            int idx = p * 256 + t;
            int row = idx >> 3, seg = idx & 7;
            uint32_t so = (uint32_t)(row * 72 + seg * 8) * 2;
            cp_async16(st + so,               Khg + (size_t)row * DH + seg * 8);
            cp_async16(st + KV_TILE + so,     Klg + (size_t)row * DH + seg * 8);
            cp_async16(st + 2 * KV_TILE + so, Vhg + (size_t)row * NTOK + seg * 8);
        }
        CP_COMMIT();
    }

#pragma unroll
    for (int p = 0; p < 4; p++) {
        int idx = p * 256 + t;
        int row = idx >> 3, seg = idx & 7;
        *(uint4*)(sQh + row * 72 + seg * 8) = *(const uint4*)(Qhg + row * DH + seg * 8);
        *(uint4*)(sQl + row * 72 + seg * 8) = *(const uint4*)(Qlg + row * DH + seg * 8);
    }

    float o[8][4] = {};
    float m0 = -1e30f, m1 = -1e30f, l0 = 0.f, l1 = 0.f;

    int arow = lane & 15, acolp = (lane >> 4) << 3;
    int brow = (lane & 7) + ((lane >> 4) & 1) * 8;
    int bcolp = ((lane >> 3) & 1) * 8;

    for (int kt = 0; kt < 16; kt++) {
        CP_WAIT(0);
        __syncthreads();
        if (kt + 1 < 16) {
            uint32_t st = sb + ATT_Q + ((kt + 1) & 1) * KV_STAGE;
            int jb = (kt + 1) * 64;
#pragma unroll
            for (int p = 0; p < 2; p++) {
                int idx = p * 256 + t;
                int row = idx >> 3, seg = idx & 7;
                uint32_t so = (uint32_t)(row * 72 + seg * 8) * 2;
                cp_async16(st + so,               Khg + (size_t)(jb + row) * DH + seg * 8);
                cp_async16(st + KV_TILE + so,     Klg + (size_t)(jb + row) * DH + seg * 8);
                cp_async16(st + 2 * KV_TILE + so, Vhg + (size_t)row * NTOK + jb + seg * 8);
            }
            CP_COMMIT();
        }

        uint32_t kv = sb + ATT_Q + (kt & 1) * KV_STAGE;

        float s[8][4] = {};
        uint32_t sc[8][2] = {};
#pragma unroll
        for (int ks = 0; ks < 4; ks++) {
            uint32_t ah[4], al[4];
            uint32_t aq = sb + oQh + ((wid * 16 + arow) * 72 + ks * 16 + acolp) * 2;
            ldsm_x4(ah, aq);
            ldsm_x4(al, aq + (oQl - oQh));
#pragma unroll
            for (int ntp = 0; ntp < 4; ntp++) {
                uint32_t bhf[4], blf[4];
                uint32_t ba = kv + ((ntp * 16 + brow) * 72 + ks * 16 + bcolp) * 2;
                ldsm_x4(bhf, ba);
                ldsm_x4(blf, ba + KV_TILE);
                int nt = ntp * 2;
                mma_f16(s[nt],     ah, &bhf[0]);
                mma_f16(s[nt + 1], ah, &bhf[2]);
                mma_f16acc(sc[nt],     al, &bhf[0]);
                mma_f16acc(sc[nt + 1], al, &bhf[2]);
                mma_f16acc(sc[nt],     ah, &blf[0]);
                mma_f16acc(sc[nt + 1], ah, &blf[2]);
            }
        }
#pragma unroll
        for (int nt = 0; nt < 8; nt++) {
            float2 c01 = h2f2(sc[nt][0]);
            float2 c23 = h2f2(sc[nt][1]);
            s[nt][0] += c01.x;
            s[nt][1] += c01.y;
            s[nt][2] += c23.x;
            s[nt][3] += c23.y;
        }

        float rm0 = -1e30f, rm1 = -1e30f;
#pragma unroll
        for (int nt = 0; nt < 8; nt++) {
            rm0 = fmaxf(rm0, fmaxf(s[nt][0], s[nt][1]));
            rm1 = fmaxf(rm1, fmaxf(s[nt][2], s[nt][3]));
        }
        rm0 = fmaxf(rm0, __shfl_xor_sync(0xffffffffu, rm0, 1));
        rm0 = fmaxf(rm0, __shfl_xor_sync(0xffffffffu, rm0, 2));
        rm1 = fmaxf(rm1, __shfl_xor_sync(0xffffffffu, rm1, 1));
        rm1 = fmaxf(rm1, __shfl_xor_sync(0xffffffffu, rm1, 2));
        float mn0 = fmaxf(m0, rm0), mn1 = fmaxf(m1, rm1);
        float alpha0 = __expf(m0 - mn0), alpha1 = __expf(m1 - mn1);
        m0 = mn0; m1 = mn1;
        float rs0 = 0.f, rs1 = 0.f;
#pragma unroll
        for (int nt = 0; nt < 8; nt++) {
            s[nt][0] = __expf(s[nt][0] - mn0);
            s[nt][1] = __expf(s[nt][1] - mn0);
            s[nt][2] = __expf(s[nt][2] - mn1);
            s[nt][3] = __expf(s[nt][3] - mn1);
            rs0 += s[nt][0] + s[nt][1];
            rs1 += s[nt][2] + s[nt][3];
        }
        rs0 += __shfl_xor_sync(0xffffffffu, rs0, 1);
        rs0 += __shfl_xor_sync(0xffffffffu, rs0, 2);
        rs1 += __shfl_xor_sync(0xffffffffu, rs1, 1);
        rs1 += __shfl_xor_sync(0xffffffffu, rs1, 2);
        l0 = l0 * alpha0 + rs0;
        l1 = l1 * alpha1 + rs1;
#pragma unroll
        for (int nt = 0; nt < 8; nt++) {
            o[nt][0] *= alpha0; o[nt][1] *= alpha0;
            o[nt][2] *= alpha1; o[nt][3] *= alpha1;
        }

        uint32_t pah[4][4];
#pragma unroll
        for (int ks = 0; ks < 4; ks++) {
#pragma unroll
            for (int q = 0; q < 4; q++) {
                int nt = ks * 2 + (q >> 1);
                pah[ks][q] = pack_f16(s[nt][(q & 1) * 2], s[nt][(q & 1) * 2 + 1]);
            }
        }

#pragma unroll
        for (int ks = 0; ks < 4; ks++) {
#pragma unroll
            for (int ntp = 0; ntp < 4; ntp++) {
                uint32_t vhf[4];
                uint32_t va = kv + 2 * KV_TILE + ((ntp * 16 + brow) * 72 + ks * 16 + bcolp) * 2;
                ldsm_x4(vhf, va);
                mma_f16(o[ntp * 2],     pah[ks], &vhf[0]);
                mma_f16(o[ntp * 2 + 1], pah[ks], &vhf[2]);
            }
        }
    }

    float inv0 = 1.f / l0, inv1 = 1.f / l1;
    int b = bh / HEADS, h = bh % HEADS;
    int r0 = qn0 + wid * 16 + (lane >> 2);
    int cb = h * DH + (lane & 3) * 2;
#pragma unroll
    for (int nt = 0; nt < 8; nt++) {
        uint32_t hp0 = pack_f16(o[nt][0] * inv0, o[nt][1] * inv0);
        uint32_t hp1 = pack_f16(o[nt][2] * inv1, o[nt][3] * inv1);
        size_t o0 = ((size_t)b * NTOK + r0) * DIMC + cb + nt * 8;
        size_t o1 = ((size_t)b * NTOK + r0 + 8) * DIMC + cb + nt * 8;
        *(uint32_t*)(g_Ch + o0) = hp0;
        *(uint32_t*)(g_Ch + o1) = hp1;
    }
}

// ---------------------------------------------------------------------------
extern "C" void kernel_launch(void* const* d_in, const int* in_sizes, int n_in,
                              void* d_out, int out_size) {
    const float* x      = (const float*)d_in[0];
    const float* w_qkv  = (const float*)d_in[1];
    const float* w_proj = (const float*)d_in[2];
    float* out = (float*)d_out;

    cudaFuncSetAttribute(qkv_mma,  cudaFuncAttributeMaxDynamicSharedMemorySize, GEMM_SMEM);
    cudaFuncSetAttribute(proj_mma, cudaFuncAttributeMaxDynamicSharedMemorySize, PROJ_SMEM);
    cudaFuncSetAttribute(attn_mma, cudaFuncAttributeMaxDynamicSharedMemorySize, ATT_SMEM);

    split_all_kernel<<<dim3(72, 24, 10), 256>>>(x, w_qkv, w_proj);
    qkv_mma <<<dim3(64, 9), GTHREADS, GEMM_SMEM>>>();
    attn_mma<<<dim3(NTOK / 128, NBH), 256, ATT_SMEM>>>();
    proj_mma<<<dim3(64, 6), GTHREADS, PROJ_SMEM>>>(out);
}